// round 1
// baseline (speedup 1.0000x reference)
#include <cuda_runtime.h>
#include <cstdint>

#define S_LEN 8192
#define C_LEN 24
#define E_DIM 512
#define H_DIM 1024
#define R_DIM 256
#define L_DIM 50
#define GATE_W (4*H_DIM)      // 4096
#define XCAT_DIM (E_DIM+R_DIM) // 768
#define RG 128                 // persistent CTAs for recurrence

// ---------------- static scratch (allocation-free rule) ----------------
__device__ float d_X[(size_t)S_LEN*GATE_W];       // precomputed x-gates + bias, 134MB
__device__ float d_Hs[(size_t)S_LEN*H_DIM];       // word-LSTM hidden states
__device__ float d_gates[(size_t)S_LEN*4*R_DIM];  // char-LSTM gate scratch
__device__ float d_xcat[(size_t)S_LEN*XCAT_DIM];  // [embed | char_rep]
__device__ float d_hchar[(size_t)S_LEN*R_DIM];
__device__ float d_cchar[(size_t)S_LEN*R_DIM];
__device__ float d_hbuf[2*H_DIM];                 // double-buffered word h
__device__ unsigned d_bar;                        // grid barrier counter

__device__ __forceinline__ float sigmf(float x){ return 1.f/(1.f+__expf(-x)); }

// ---------------- init ----------------
__global__ void init_kernel()
{
    int i = blockIdx.x*blockDim.x + threadIdx.x;
    if (i == 0) d_bar = 0u;
    if (i < 2*H_DIM) d_hbuf[i] = 0.f;
    int n = S_LEN*R_DIM;
    for (int k = i; k < n; k += gridDim.x*blockDim.x){
        d_hchar[k] = 0.f;
        d_cchar[k] = 0.f;
    }
}

// ---------------- fp32 tiled GEMM: C[M,N] = A[M,K] * B[N,K]^T (+bias[N]) ----------------
__global__ __launch_bounds__(256) void sgemm_nt(
    const float* __restrict__ A, const float* __restrict__ B,
    float* __restrict__ C, const float* __restrict__ bias,
    int M, int N, int K)
{
    __shared__ float As[16][68];   // [kk][m], pad 68 -> 272B rows (16B aligned)
    __shared__ float Bs[16][68];
    const int bn = blockIdx.x*64, bm = blockIdx.y*64;
    const int tid = threadIdx.x;
    const int tx = tid & 15, ty = tid >> 4;
    const int lr = tid >> 2, lk = (tid & 3) << 2;

    float acc[4][4];
    #pragma unroll
    for (int i=0;i<4;i++)
        #pragma unroll
        for (int j=0;j<4;j++) acc[i][j] = 0.f;

    const float* Ab = A + (size_t)(bm+lr)*K + lk;
    const float* Bb = B + (size_t)(bn+lr)*K + lk;

    for (int k0 = 0; k0 < K; k0 += 16){
        float4 av = *(const float4*)(Ab + k0);
        float4 bv = *(const float4*)(Bb + k0);
        As[lk+0][lr]=av.x; As[lk+1][lr]=av.y; As[lk+2][lr]=av.z; As[lk+3][lr]=av.w;
        Bs[lk+0][lr]=bv.x; Bs[lk+1][lr]=bv.y; Bs[lk+2][lr]=bv.z; Bs[lk+3][lr]=bv.w;
        __syncthreads();
        #pragma unroll
        for (int kk=0;kk<16;kk++){
            float4 a4 = *(const float4*)&As[kk][ty<<2];
            float4 b4 = *(const float4*)&Bs[kk][tx<<2];
            float a[4] = {a4.x,a4.y,a4.z,a4.w};
            float b[4] = {b4.x,b4.y,b4.z,b4.w};
            #pragma unroll
            for (int i=0;i<4;i++)
                #pragma unroll
                for (int j=0;j<4;j++) acc[i][j] = fmaf(a[i], b[j], acc[i][j]);
        }
        __syncthreads();
    }

    #pragma unroll
    for (int i=0;i<4;i++){
        int m = bm + (ty<<2) + i;
        #pragma unroll
        for (int j=0;j<4;j++){
            int n = bn + (tx<<2) + j;
            float v = acc[i][j];
            if (bias) v += bias[n];
            C[(size_t)m*N + n] = v;
        }
    }
}

// ---------------- char-LSTM pointwise update (after gates GEMM) ----------------
__global__ __launch_bounds__(256) void char_update(
    const float* __restrict__ chars,
    const float* __restrict__ Wc_ih,
    const float* __restrict__ bc,
    int step)
{
    int idx = blockIdx.x*blockDim.x + threadIdx.x;
    if (idx >= S_LEN*R_DIM) return;
    int r = idx & (R_DIM-1);
    int s = idx >> 8;
    float x = chars[s*C_LEN + step];
    const float* g = d_gates + (size_t)s*4*R_DIM;
    float gi = g[r]           + Wc_ih[r]          *x + bc[r];
    float gf = g[R_DIM+r]     + Wc_ih[R_DIM+r]    *x + bc[R_DIM+r];
    float gg = g[2*R_DIM+r]   + Wc_ih[2*R_DIM+r]  *x + bc[2*R_DIM+r];
    float go = g[3*R_DIM+r]   + Wc_ih[3*R_DIM+r]  *x + bc[3*R_DIM+r];
    float c = d_cchar[idx];
    c = sigmf(gf)*c + sigmf(gi)*tanhf(gg);
    d_cchar[idx] = c;
    d_hchar[idx] = sigmf(go)*tanhf(c);
}

// ---------------- embed gather + concat with char_rep ----------------
__global__ __launch_bounds__(256) void gather_concat(
    const int* __restrict__ sentence,
    const float* __restrict__ embed)
{
    int idx = blockIdx.x*blockDim.x + threadIdx.x;
    if (idx >= S_LEN*XCAT_DIM) return;
    int c = idx % XCAT_DIM;
    int s = idx / XCAT_DIM;
    d_xcat[idx] = (c < E_DIM)
        ? embed[(size_t)sentence[s]*E_DIM + c]
        : d_hchar[s*R_DIM + (c - E_DIM)];
}

// ---------------- persistent word-LSTM recurrence ----------------
// 128 CTAs x 512 threads. CTA owns h indices [cta*8, cta*8+8).
// Warp w handles 2 gate rows; Whh rows live in registers (64 f32/thread).
__global__ __launch_bounds__(512, 1) void word_recur(const float* __restrict__ Whh)
{
    const int cta  = blockIdx.x;
    const int w    = threadIdx.x >> 5;
    const int lane = threadIdx.x & 31;
    const int p0 = 2*w, p1 = 2*w + 1;        // local gate-row ids, p = 4*lh + g
    const int lh = p0 >> 2;
    const int g0 = p0 & 3, g1 = p1 & 3;
    const int j0 = g0*H_DIM + cta*8 + lh;    // global gate rows (i,f,g,o blocks)
    const int j1 = g1*H_DIM + cta*8 + lh;

    // Load recurrent weights into registers (k = 4*(lane + 32*i) + c layout)
    float4 w0q[8], w1q[8];
    const float4* W0 = (const float4*)(Whh + (size_t)j0*H_DIM);
    const float4* W1 = (const float4*)(Whh + (size_t)j1*H_DIM);
    #pragma unroll
    for (int i=0;i<8;i++){ w0q[i] = W0[lane + 32*i]; w1q[i] = W1[lane + 32*i]; }

    __shared__ float gsm[32];
    __shared__ float csm[8];
    if (threadIdx.x < 8) csm[threadIdx.x] = 0.f;

    // prefetch X for step 0 (includes bw bias from the precompute GEMM)
    float xv0 = d_X[j0];
    float xv1 = d_X[j1];
    __syncthreads();

    for (int t = 0; t < S_LEN; t++){
        // h broadcast: MUST bypass L1 (buffer alternates every step; L1 persists in-launch)
        const float4* h4 = (const float4*)(d_hbuf + (t & 1)*H_DIM);
        float4 hq[8];
        #pragma unroll
        for (int i=0;i<8;i++) hq[i] = __ldcg(h4 + lane + 32*i);

        // software prefetch of next step's X (hidden under FMA + barrier)
        float nx0 = 0.f, nx1 = 0.f;
        if (t + 1 < S_LEN){
            nx0 = __ldg(&d_X[(size_t)(t+1)*GATE_W + j0]);
            nx1 = __ldg(&d_X[(size_t)(t+1)*GATE_W + j1]);
        }

        float a0 = 0.f, a1 = 0.f;
        #pragma unroll
        for (int i=0;i<8;i++){
            a0 = fmaf(hq[i].x, w0q[i].x, a0); a0 = fmaf(hq[i].y, w0q[i].y, a0);
            a0 = fmaf(hq[i].z, w0q[i].z, a0); a0 = fmaf(hq[i].w, w0q[i].w, a0);
            a1 = fmaf(hq[i].x, w1q[i].x, a1); a1 = fmaf(hq[i].y, w1q[i].y, a1);
            a1 = fmaf(hq[i].z, w1q[i].z, a1); a1 = fmaf(hq[i].w, w1q[i].w, a1);
        }
        #pragma unroll
        for (int m=16;m>0;m>>=1){
            a0 += __shfl_xor_sync(0xffffffffu, a0, m);
            a1 += __shfl_xor_sync(0xffffffffu, a1, m);
        }
        if (lane == 0){ gsm[p0] = a0 + xv0; gsm[p1] = a1 + xv1; }
        __syncthreads();

        if (threadIdx.x < 8){
            int l = threadIdx.x;
            float gi = gsm[4*l+0], gf = gsm[4*l+1], gg = gsm[4*l+2], go = gsm[4*l+3];
            float c = sigmf(gf)*csm[l] + sigmf(gi)*tanhf(gg);
            csm[l] = c;
            float hv = sigmf(go)*tanhf(c);
            int hidx = cta*8 + l;
            d_hbuf[((t+1) & 1)*H_DIM + hidx] = hv;
            d_Hs[(size_t)t*H_DIM + hidx] = hv;
        }
        __syncthreads();

        // grid barrier: release-add, acquire-poll
        if (threadIdx.x == 0){
            __threadfence();
            atomicAdd(&d_bar, 1u);
            unsigned target = (unsigned)RG*(unsigned)(t+1);
            unsigned v;
            do {
                asm volatile("ld.global.acquire.gpu.u32 %0, [%1];"
                             : "=r"(v) : "l"(&d_bar) : "memory");
            } while (v < target);
        }
        __syncthreads();

        xv0 = nx0; xv1 = nx1;
    }
}

// ---------------- output layer + log_softmax ----------------
__global__ __launch_bounds__(128) void out_kernel(
    const float* __restrict__ Wout,
    const float* __restrict__ bout,
    float* __restrict__ out)
{
    int s = blockIdx.x;
    __shared__ float hrow[H_DIM];
    __shared__ float e[64];
    __shared__ float s_lse;
    int tid = threadIdx.x;

    const float4* Hs4 = (const float4*)(d_Hs + (size_t)s*H_DIM);
    ((float4*)hrow)[tid*2]   = Hs4[tid*2];
    ((float4*)hrow)[tid*2+1] = Hs4[tid*2+1];
    __syncthreads();

    int warp = tid >> 5, lane = tid & 31;
    for (int l = warp; l < L_DIM; l += 4){
        const float* wr = Wout + (size_t)l*H_DIM;
        float sum = 0.f;
        for (int k = lane; k < H_DIM; k += 32) sum = fmaf(hrow[k], wr[k], sum);
        #pragma unroll
        for (int m=16;m>0;m>>=1) sum += __shfl_xor_sync(0xffffffffu, sum, m);
        if (lane == 0) e[l] = sum + bout[l];
    }
    __syncthreads();

    if (tid < 32){
        float mx = -1e30f;
        for (int l = tid; l < L_DIM; l += 32) mx = fmaxf(mx, e[l]);
        #pragma unroll
        for (int m=16;m>0;m>>=1) mx = fmaxf(mx, __shfl_xor_sync(0xffffffffu, mx, m));
        float sum = 0.f;
        for (int l = tid; l < L_DIM; l += 32) sum += __expf(e[l]-mx);
        #pragma unroll
        for (int m=16;m>0;m>>=1) sum += __shfl_xor_sync(0xffffffffu, sum, m);
        if (tid == 0) s_lse = mx + logf(sum);
    }
    __syncthreads();

    for (int l = tid; l < L_DIM; l += 128)
        out[(size_t)s*L_DIM + l] = e[l] - s_lse;
}

// ---------------- launch ----------------
extern "C" void kernel_launch(void* const* d_in, const int* in_sizes, int n_in,
                              void* d_out, int out_size)
{
    const int*   sentence = (const int*)  d_in[0];
    const float* chars    = (const float*)d_in[1];
    const float* embed    = (const float*)d_in[2];
    const float* Wc_ih    = (const float*)d_in[3];
    const float* Wc_hh    = (const float*)d_in[4];
    const float* bc       = (const float*)d_in[5];
    const float* Ww_ih    = (const float*)d_in[6];
    const float* Ww_hh    = (const float*)d_in[7];
    const float* bw       = (const float*)d_in[8];
    const float* Wout     = (const float*)d_in[9];
    const float* bout     = (const float*)d_in[10];
    float* out = (float*)d_out;

    float *pX, *pGates, *pXcat, *pHchar;
    cudaGetSymbolAddress((void**)&pX,     d_X);
    cudaGetSymbolAddress((void**)&pGates, d_gates);
    cudaGetSymbolAddress((void**)&pXcat,  d_xcat);
    cudaGetSymbolAddress((void**)&pHchar, d_hchar);

    init_kernel<<<1024, 256>>>();

    // char-level LSTM: gates GEMM + pointwise, 24 steps
    dim3 gChar(4*R_DIM/64, S_LEN/64);     // (16, 128)
    int pwBlocks = (S_LEN*R_DIM + 255)/256;
    for (int step = 0; step < C_LEN; step++){
        sgemm_nt<<<gChar, 256>>>(pHchar, Wc_hh, pGates, nullptr,
                                 S_LEN, 4*R_DIM, R_DIM);
        char_update<<<pwBlocks, 256>>>(chars, Wc_ih, bc, step);
    }

    // concat [embed(sentence) | char_rep]
    int gcBlocks = (S_LEN*XCAT_DIM + 255)/256;
    gather_concat<<<gcBlocks, 256>>>(sentence, embed);

    // precompute word-LSTM x-gates: X = xcat @ Ww_ih^T + bw
    dim3 gPre(GATE_W/64, S_LEN/64);       // (64, 128)
    sgemm_nt<<<gPre, 256>>>(pXcat, Ww_ih, pX, bw,
                            S_LEN, GATE_W, XCAT_DIM);

    // sequential word-LSTM recurrence (persistent kernel, grid barrier per step)
    word_recur<<<RG, 512>>>(Ww_hh);

    // output layer + log_softmax
    out_kernel<<<S_LEN, 128>>>(Wout, bout, out);
}